// round 1
// baseline (speedup 1.0000x reference)
#include <cuda_runtime.h>

#define DIMS 64
#define CHUNK 128
#define TPB 256
#define MAXBLOCKS 8192

// Scratch (no allocations allowed): codebook squared norms + loss partials.
__device__ float  g_csum[8192];
__device__ double g_partials[MAXBLOCKS];

// ---------------------------------------------------------------------------
// Kernel 1: c_k = ||e_k||^2 (order irrelevant: c ~ 2e-5 added to ~64, any
// few-ulp difference cannot cross an ulp(64) rounding boundary).
// ---------------------------------------------------------------------------
__global__ void vq_precompute_c(const float* __restrict__ cb, int K) {
    int k = blockIdx.x * blockDim.x + threadIdx.x;
    if (k >= K) return;
    const float4* r = (const float4*)(cb + (size_t)k * DIMS);
    float c = 0.f;
#pragma unroll
    for (int j = 0; j < DIMS / 4; j++) {
        float4 v = r[j];
        c = __fadd_rn(c, __fmul_rn(v.x, v.x));
        c = __fadd_rn(c, __fmul_rn(v.y, v.y));
        c = __fadd_rn(c, __fmul_rn(v.z, v.z));
        c = __fadd_rn(c, __fmul_rn(v.w, v.w));
    }
    g_csum[k] = c;
}

// ---------------------------------------------------------------------------
// Kernel 2: per-point argmin over the codebook + quantized output + fp64
// partial loss sums. One point per thread; x held in registers; codebook
// streamed through shared memory in CHUNK-row tiles (warp-broadcast reads).
//
// Score replicates JAX exactly: s = fl( fl(A - 2*d) + c ), with
//   A = ||x||^2 computed as a strictly SEQUENTIAL non-FMA fp32 sum
//       (XLA CPU cannot reassociate fp reductions without fast-math),
//   d = x.e in fp32 FMA (reorder noise ~1e-9, harmless vs ulp(64) grid),
//   argmin tie-break = lowest index (ascending k, strict <).
// ---------------------------------------------------------------------------
__global__ __launch_bounds__(TPB, 2)
void vq_main(const float* __restrict__ x_g, const float* __restrict__ cb,
             float* __restrict__ out, int N, int K) {
    __shared__ float  sm_cb[CHUNK * DIMS];
    __shared__ float  sm_c[CHUNK];
    __shared__ double sm_red[TPB];

    const int n = blockIdx.x * TPB + threadIdx.x;
    const bool active = (n < N);

    float4 xr[DIMS / 4];
    float A = 0.f;
    if (active) {
        const float4* xrow = (const float4*)(x_g + (size_t)n * DIMS);
#pragma unroll
        for (int j = 0; j < DIMS / 4; j++) xr[j] = xrow[j];
        // Sequential, non-fused ||x||^2 to match XLA's in-order reduction.
#pragma unroll
        for (int j = 0; j < DIMS / 4; j++) {
            A = __fadd_rn(A, __fmul_rn(xr[j].x, xr[j].x));
            A = __fadd_rn(A, __fmul_rn(xr[j].y, xr[j].y));
            A = __fadd_rn(A, __fmul_rn(xr[j].z, xr[j].z));
            A = __fadd_rn(A, __fmul_rn(xr[j].w, xr[j].w));
        }
    }

    float best = 3.402823466e38f;
    int   besti = 0;

    for (int kb = 0; kb < K; kb += CHUNK) {
        // Cooperative, coalesced tile load.
        const float4* src = (const float4*)(cb + (size_t)kb * DIMS);
        for (int i = threadIdx.x; i < CHUNK * DIMS / 4; i += TPB)
            ((float4*)sm_cb)[i] = src[i];
        for (int i = threadIdx.x; i < CHUNK; i += TPB)
            sm_c[i] = g_csum[kb + i];
        __syncthreads();

        if (active) {
            for (int kk = 0; kk < CHUNK; kk++) {
                const float4* e4 = (const float4*)(sm_cb + kk * DIMS);
                float a0 = 0.f, a1 = 0.f, a2 = 0.f, a3 = 0.f;
#pragma unroll
                for (int j = 0; j < DIMS / 4; j++) {
                    float4 v = e4[j];
                    a0 = fmaf(xr[j].x, v.x, a0);
                    a1 = fmaf(xr[j].y, v.y, a1);
                    a2 = fmaf(xr[j].z, v.z, a2);
                    a3 = fmaf(xr[j].w, v.w, a3);
                }
                float d = __fadd_rn(__fadd_rn(a0, a1), __fadd_rn(a2, a3));
                // 2*d is exact (power of two); fl(A-2d) then fl(.+c) match JAX.
                float s = __fadd_rn(__fsub_rn(A, 2.0f * d), sm_c[kk]);
                if (s < best) { best = s; besti = kb + kk; }
            }
        }
        __syncthreads();
    }

    // Gather winner, emit quantized output, accumulate fp64 loss partial.
    double lsum = 0.0;
    if (active) {
        const float4* q4 = (const float4*)(cb + (size_t)besti * DIMS);
        float4* o4 = (float4*)(out + (size_t)n * DIMS);
#pragma unroll
        for (int j = 0; j < DIMS / 4; j++) {
            float4 q = q4[j];
            o4[j] = q;
            float dx = __fsub_rn(q.x, xr[j].x); lsum += (double)__fmul_rn(dx, dx);
            float dy = __fsub_rn(q.y, xr[j].y); lsum += (double)__fmul_rn(dy, dy);
            float dz = __fsub_rn(q.z, xr[j].z); lsum += (double)__fmul_rn(dz, dz);
            float dw = __fsub_rn(q.w, xr[j].w); lsum += (double)__fmul_rn(dw, dw);
        }
    }

    // Deterministic in-block tree reduction (fp64), one partial per CTA.
    sm_red[threadIdx.x] = lsum;
    __syncthreads();
    for (int s = TPB / 2; s > 0; s >>= 1) {
        if (threadIdx.x < s) sm_red[threadIdx.x] += sm_red[threadIdx.x + s];
        __syncthreads();
    }
    if (threadIdx.x == 0) g_partials[blockIdx.x] = sm_red[0];
}

// ---------------------------------------------------------------------------
// Kernel 3: deterministic (fixed-order) final loss reduction.
// loss = m + 0.25*m with m = fl32(mean), matching the reference expression.
// ---------------------------------------------------------------------------
__global__ void vq_finalize(float* __restrict__ out, int nblocks,
                            long long total, int loss_off) {
    if (threadIdx.x == 0 && blockIdx.x == 0) {
        double s = 0.0;
        for (int i = 0; i < nblocks; i++) s += g_partials[i];
        float m = (float)(s / (double)total);
        out[loss_off] = __fadd_rn(m, __fmul_rn(0.25f, m));
    }
}

// ---------------------------------------------------------------------------
extern "C" void kernel_launch(void* const* d_in, const int* in_sizes, int n_in,
                              void* d_out, int out_size) {
    const float* x  = (const float*)d_in[0];   // inputs   [32,4096,64] fp32
    const float* cb = (const float*)d_in[1];   // codebook [1024,64]    fp32
    float* out = (float*)d_out;                // [N*D quantized ..., loss]

    const int ND = in_sizes[0];
    const int KD = in_sizes[1];
    const int N = ND / DIMS;
    const int K = KD / DIMS;

    int nb = (N + TPB - 1) / TPB;              // 512 blocks for this shape
    if (nb > MAXBLOCKS) nb = MAXBLOCKS;        // (not reachable at this size)

    vq_precompute_c<<<(K + 255) / 256, 256>>>(cb, K);
    vq_main<<<nb, TPB>>>(x, cb, out, N, K);
    vq_finalize<<<1, 32>>>(out, nb, (long long)ND, ND);
}

// round 3
// speedup vs baseline: 1.1201x; 1.1201x over previous
#include <cuda_runtime.h>

#define DIMS 64
#define CHUNK 128
#define TPB 256
#define MAXBLOCKS 8192

typedef unsigned long long u64;

// Scratch (no allocations allowed): codebook squared norms + loss partials.
__device__ float  g_csum[8192];
__device__ double g_partials[MAXBLOCKS];

// Packed f32x2 ops (sm_100+). Two independent IEEE fp32 lanes per instruction.
#define FMA_F32X2(d, a, b, c) \
    asm("fma.rn.f32x2 %0, %1, %2, %3;" : "=l"(d) : "l"(a), "l"(b), "l"(c))
#define ADD_F32X2(d, a, b) \
    asm("add.rn.f32x2 %0, %1, %2;" : "=l"(d) : "l"(a), "l"(b))
#define PACK_F32X2(d, lo, hi) \
    asm("mov.b64 %0, {%1, %2};" : "=l"(d) : "f"(lo), "f"(hi))
#define UNPACK_F32X2(lo, hi, s) \
    asm("mov.b64 {%0, %1}, %2;" : "=f"(lo), "=f"(hi) : "l"(s))

// ---------------------------------------------------------------------------
// Kernel 1: c_k = ||e_k||^2 (order-insensitive: c ~ 2e-5 added to ~64; a few
// ulp of c cannot cross an ulp(64) boundary of the final score).
// ---------------------------------------------------------------------------
__global__ void vq_precompute_c(const float* __restrict__ cb, int K) {
    int k = blockIdx.x * blockDim.x + threadIdx.x;
    if (k >= K) return;
    const float4* r = (const float4*)(cb + (size_t)k * DIMS);
    float c = 0.f;
#pragma unroll
    for (int j = 0; j < DIMS / 4; j++) {
        float4 v = r[j];
        c = __fadd_rn(c, __fmul_rn(v.x, v.x));
        c = __fadd_rn(c, __fmul_rn(v.y, v.y));
        c = __fadd_rn(c, __fmul_rn(v.z, v.z));
        c = __fadd_rn(c, __fmul_rn(v.w, v.w));
    }
    g_csum[k] = c;
}

// ---------------------------------------------------------------------------
// Kernel 2: per-point argmin via packed-FFMA2 dot products.
// Score s = fl( fl(A - 2*d) + c ):
//   A  = sequential non-FMA fp32 sum (validated in R1: 0 argmin flips),
//   d  = fp32-FMA dot with an 8-way lane split (4 packed f32x2 accumulators),
//        abs perturbation vs R1 ~1e-9 << near-tie spacing,
//   tie-break = lowest index (ascending k, strict <) = jnp.argmin.
// ---------------------------------------------------------------------------
__global__ __launch_bounds__(TPB, 2)
void vq_main(const float* __restrict__ x_g, const float* __restrict__ cb,
             float* __restrict__ out, int N, int K) {
    __shared__ float  sm_cb[CHUNK * DIMS];
    __shared__ float  sm_c[CHUNK];
    __shared__ double sm_red[TPB];

    const int n = blockIdx.x * TPB + threadIdx.x;
    const bool active = (n < N);

    float4 xr[DIMS / 4];
    u64    xp[DIMS / 2];        // packed (x[2j], x[2j+1])
    float  A = 0.f;
    if (active) {
        const float4* xrow = (const float4*)(x_g + (size_t)n * DIMS);
#pragma unroll
        for (int j = 0; j < DIMS / 4; j++) xr[j] = xrow[j];
        // Sequential, non-fused ||x||^2 (matches R1-validated rounding).
#pragma unroll
        for (int j = 0; j < DIMS / 4; j++) {
            A = __fadd_rn(A, __fmul_rn(xr[j].x, xr[j].x));
            A = __fadd_rn(A, __fmul_rn(xr[j].y, xr[j].y));
            A = __fadd_rn(A, __fmul_rn(xr[j].z, xr[j].z));
            A = __fadd_rn(A, __fmul_rn(xr[j].w, xr[j].w));
        }
#pragma unroll
        for (int j = 0; j < DIMS / 4; j++) {
            PACK_F32X2(xp[2 * j],     xr[j].x, xr[j].y);
            PACK_F32X2(xp[2 * j + 1], xr[j].z, xr[j].w);
        }
    }

    float best = 3.402823466e38f;
    int   besti = 0;

    for (int kb = 0; kb < K; kb += CHUNK) {
        // Cooperative, coalesced tile load of the codebook chunk.
        const float4* src = (const float4*)(cb + (size_t)kb * DIMS);
        for (int i = threadIdx.x; i < CHUNK * DIMS / 4; i += TPB)
            ((float4*)sm_cb)[i] = src[i];
        for (int i = threadIdx.x; i < CHUNK; i += TPB)
            sm_c[i] = g_csum[kb + i];
        __syncthreads();

        if (active) {
            for (int kk = 0; kk < CHUNK; kk++) {
                // 16 LDS.128 (broadcast) delivering 32 packed f32x2 operands.
                const ulonglong2* e2 = (const ulonglong2*)(sm_cb + kk * DIMS);
                u64 P0 = 0ull, P1 = 0ull, P2 = 0ull, P3 = 0ull;
#pragma unroll
                for (int j = 0; j < DIMS / 8; j++) {      // 8 groups of 8 dims
                    ulonglong2 ea = e2[2 * j];
                    ulonglong2 eb = e2[2 * j + 1];
                    FMA_F32X2(P0, xp[4 * j],     ea.x, P0);
                    FMA_F32X2(P1, xp[4 * j + 1], ea.y, P1);
                    FMA_F32X2(P2, xp[4 * j + 2], eb.x, P2);
                    FMA_F32X2(P3, xp[4 * j + 3], eb.y, P3);
                }
                u64 s01, s23, st;
                ADD_F32X2(s01, P0, P1);
                ADD_F32X2(s23, P2, P3);
                ADD_F32X2(st, s01, s23);
                float dl, dh;
                UNPACK_F32X2(dl, dh, st);
                float d = __fadd_rn(dl, dh);
                // 2*d exact (power of two); fl(A-2d) then fl(.+c) match JAX.
                float s = __fadd_rn(__fsub_rn(A, 2.0f * d), sm_c[kk]);
                if (s < best) { best = s; besti = kb + kk; }
            }
        }
        __syncthreads();
    }

    // Gather winner, emit quantized output, accumulate fp64 loss partial.
    double lsum = 0.0;
    if (active) {
        const float4* q4 = (const float4*)(cb + (size_t)besti * DIMS);
        float4* o4 = (float4*)(out + (size_t)n * DIMS);
#pragma unroll
        for (int j = 0; j < DIMS / 4; j++) {
            float4 q = q4[j];
            o4[j] = q;
            float dx = __fsub_rn(q.x, xr[j].x); lsum += (double)__fmul_rn(dx, dx);
            float dy = __fsub_rn(q.y, xr[j].y); lsum += (double)__fmul_rn(dy, dy);
            float dz = __fsub_rn(q.z, xr[j].z); lsum += (double)__fmul_rn(dz, dz);
            float dw = __fsub_rn(q.w, xr[j].w); lsum += (double)__fmul_rn(dw, dw);
        }
    }

    // Deterministic in-block tree reduction (fp64), one partial per CTA.
    sm_red[threadIdx.x] = lsum;
    __syncthreads();
    for (int s = TPB / 2; s > 0; s >>= 1) {
        if (threadIdx.x < s) sm_red[threadIdx.x] += sm_red[threadIdx.x + s];
        __syncthreads();
    }
    if (threadIdx.x == 0) g_partials[blockIdx.x] = sm_red[0];
}

// ---------------------------------------------------------------------------
// Kernel 3: deterministic (fixed-order) final loss reduction.
// loss = m + 0.25*m with m = fl32(mean), matching the reference expression.
// ---------------------------------------------------------------------------
__global__ void vq_finalize(float* __restrict__ out, int nblocks,
                            long long total, int loss_off) {
    if (threadIdx.x == 0 && blockIdx.x == 0) {
        double s = 0.0;
        for (int i = 0; i < nblocks; i++) s += g_partials[i];
        float m = (float)(s / (double)total);
        out[loss_off] = __fadd_rn(m, __fmul_rn(0.25f, m));
    }
}

// ---------------------------------------------------------------------------
extern "C" void kernel_launch(void* const* d_in, const int* in_sizes, int n_in,
                              void* d_out, int out_size) {
    const float* x  = (const float*)d_in[0];   // inputs   [32,4096,64] fp32
    const float* cb = (const float*)d_in[1];   // codebook [1024,64]    fp32
    float* out = (float*)d_out;                // [N*D quantized ..., loss]

    const int ND = in_sizes[0];
    const int KD = in_sizes[1];
    const int N = ND / DIMS;
    const int K = KD / DIMS;

    int nb = (N + TPB - 1) / TPB;              // 512 blocks for this shape
    if (nb > MAXBLOCKS) nb = MAXBLOCKS;

    vq_precompute_c<<<(K + 255) / 256, 256>>>(cb, K);
    vq_main<<<nb, TPB>>>(x, cb, out, N, K);
    vq_finalize<<<1, 32>>>(out, nb, (long long)ND, ND);
}